// round 3
// baseline (speedup 1.0000x reference)
#include <cuda_runtime.h>

#define BB 32
#define LL 64
#define CC 4
#define NPAIRS 2016          // L*(L-1)/2
#define CHUNKS 32            // blocks per batch
#define PAIRS_PER_BLOCK 64   // 256 threads / 4 lanes-per-pair

// Cross-block reduction scratch (zero at module load; kernel self-resets,
// so every call — correctness, capture, each graph replay — sees zeros).
__device__ float    g_acc[BB];
__device__ unsigned g_cnt[BB];

__global__ void __launch_bounds__(256) gp_kernel(
        const float* __restrict__ x,
        const float* __restrict__ th0,
        const float* __restrict__ th1,
        const float* __restrict__ th2,
        const float* __restrict__ th3,
        float* __restrict__ out) {
    const int b     = blockIdx.x >> 5;       // / CHUNKS
    const int chunk = blockIdx.x & 31;       // % CHUNKS
    const int tid   = threadIdx.x;
    const int sub   = tid & 3;               // lane within pair-group
    const int p     = chunk * PAIRS_PER_BLOCK + (tid >> 2);

    __shared__ float4 sx[LL];     // x_b as float4 per position
    __shared__ int    so[LL];     // flattened one-hot offsets o = l*4+c
    __shared__ float  wsum[8];

    if (tid < LL) {
        float4 v = ((const float4*)x)[b * LL + tid];
        sx[tid] = v;
        int c = v.y > 0.5f ? 1 : (v.z > 0.5f ? 2 : (v.w > 0.5f ? 3 : 0));
        so[tid] = tid * CC + c;
    }
    __syncthreads();

    float acc = 0.f;

    if (p < NPAIRS) {
        // branchless decode: p = l1*(l1-1)/2 + l0, l0 < l1
        int l1 = (int)((1.0f + sqrtf(8.0f * (float)p + 1.0f)) * 0.5f);
        if ((l1 * (l1 - 1)) >> 1 > p) l1--;
        if (((l1 + 1) * l1) >> 1 <= p) l1++;
        const int l0 = p - ((l1 * (l1 - 1)) >> 1);

        const int base2 = so[l0] * 256 + so[l1];
        // early-issue order-2 load (independent of the loop below)
        float t2 = (sub == 0) ? __ldg(&th2[base2]) : 0.f;

        const float4* __restrict__ row4 = (const float4*)th3 + (size_t)base2 * 64;

        float4 a0 = make_float4(0.f, 0.f, 0.f, 0.f);
        float4 a1 = make_float4(0.f, 0.f, 0.f, 0.f);

        int l2 = l1 + 1 + sub;
        // 4-deep batched loads: 4 independent float4 loads in flight
        for (; l2 + 12 < LL; l2 += 16) {
            float4 r0 = __ldcs(&row4[l2]);
            float4 r1 = __ldcs(&row4[l2 + 4]);
            float4 r2 = __ldcs(&row4[l2 + 8]);
            float4 r3 = __ldcs(&row4[l2 + 12]);
            float4 x0 = sx[l2];
            float4 x1 = sx[l2 + 4];
            float4 x2 = sx[l2 + 8];
            float4 x3 = sx[l2 + 12];
            a0.x = fmaf(r0.x, x0.x, a0.x); a0.y = fmaf(r0.y, x0.y, a0.y);
            a0.z = fmaf(r0.z, x0.z, a0.z); a0.w = fmaf(r0.w, x0.w, a0.w);
            a1.x = fmaf(r1.x, x1.x, a1.x); a1.y = fmaf(r1.y, x1.y, a1.y);
            a1.z = fmaf(r1.z, x1.z, a1.z); a1.w = fmaf(r1.w, x1.w, a1.w);
            a0.x = fmaf(r2.x, x2.x, a0.x); a0.y = fmaf(r2.y, x2.y, a0.y);
            a0.z = fmaf(r2.z, x2.z, a0.z); a0.w = fmaf(r2.w, x2.w, a0.w);
            a1.x = fmaf(r3.x, x3.x, a1.x); a1.y = fmaf(r3.y, x3.y, a1.y);
            a1.z = fmaf(r3.z, x3.z, a1.z); a1.w = fmaf(r3.w, x3.w, a1.w);
        }
        for (; l2 < LL; l2 += 4) {
            float4 r = __ldcs(&row4[l2]);
            float4 xv = sx[l2];
            a0.x = fmaf(r.x, xv.x, a0.x); a0.y = fmaf(r.y, xv.y, a0.y);
            a0.z = fmaf(r.z, xv.z, a0.z); a0.w = fmaf(r.w, xv.w, a0.w);
        }
        acc = t2 + (a0.x + a0.y) + (a0.z + a0.w)
                 + (a1.x + a1.y) + (a1.z + a1.w);
    }

    // order 0 + 1, folded into chunk-0 blocks (first 64 threads)
    if (chunk == 0 && tid < LL) {
        acc += th1[so[tid]];
        if (tid == 0) acc += th0[0];
    }

    // intra-block reduction
    #pragma unroll
    for (int off = 16; off > 0; off >>= 1)
        acc += __shfl_xor_sync(0xffffffffu, acc, off);
    const int warp = tid >> 5;
    if ((tid & 31) == 0) wsum[warp] = acc;
    __syncthreads();

    // cross-block: atomicAdd partial; last block for this batch finalizes
    if (tid == 0) {
        float t = 0.f;
        #pragma unroll
        for (int w = 0; w < 8; w++) t += wsum[w];
        atomicAdd(&g_acc[b], t);
        __threadfence();
        unsigned done = atomicAdd(&g_cnt[b], 1u);
        if (done == CHUNKS - 1) {
            __threadfence();
            out[b] = g_acc[b];
            g_acc[b] = 0.f;      // reset for next replay
            g_cnt[b] = 0u;
        }
    }
}

extern "C" void kernel_launch(void* const* d_in, const int* in_sizes, int n_in,
                              void* d_out, int out_size) {
    const float* x   = (const float*)d_in[0];   // (B, L*C) one-hot
    const float* th0 = (const float*)d_in[1];   // (1,)
    const float* th1 = (const float*)d_in[2];   // (L, C)
    const float* th2 = (const float*)d_in[3];   // (L*C, L*C)
    const float* th3 = (const float*)d_in[4];   // (L*C, L*C, L*C)
    float* out = (float*)d_out;                 // (B, 1)

    gp_kernel<<<BB * CHUNKS, 256>>>(x, th0, th1, th2, th3, out);
}

// round 5
// speedup vs baseline: 1.1875x; 1.1875x over previous
#include <cuda_runtime.h>

#define BB 32
#define LL 64
#define CC 4
#define NPAIRS 2016          // L*(L-1)/2
#define CHUNKS 32            // blocks per batch

// Cross-block reduction scratch (zero at module load; kernel self-resets,
// so every call — correctness, capture, each graph replay — sees zeros).
__device__ float    g_acc[BB];
__device__ unsigned g_cnt[BB];

__global__ void __launch_bounds__(256) gp_kernel(
        const float* __restrict__ x,
        const float* __restrict__ th0,
        const float* __restrict__ th1,
        const float* __restrict__ th2,
        const float* __restrict__ th3,
        float* __restrict__ out) {
    const int b     = blockIdx.x >> 5;       // / CHUNKS
    const int chunk = blockIdx.x & 31;       // % CHUNKS
    const int tid   = threadIdx.x;
    const int sub   = tid & 3;               // lane within pair-group
    const int q     = tid >> 2;              // pair-slot in block [0,64)
    const int w     = q >> 3;                // warp [0,8)
    const int qi    = q & 7;                 // pair-slot in warp [0,8)
    // Interleaved mapping: consecutive pairs within a warp (uniform trip
    // count), warps/chunks strided across the full l1 range (block balance).
    const int p     = w * 256 + chunk * 8 + qi;

    __shared__ float4 sx[LL];     // x_b as float4 per position
    __shared__ int    so[LL];     // flattened one-hot offsets o = l*4+c
    __shared__ float  wsum[8];

    if (tid < LL) {
        float4 v = ((const float4*)x)[b * LL + tid];
        sx[tid] = v;
        int c = v.y > 0.5f ? 1 : (v.z > 0.5f ? 2 : (v.w > 0.5f ? 3 : 0));
        so[tid] = tid * CC + c;
    }
    __syncthreads();

    float acc = 0.f;

    if (p < NPAIRS) {
        // branchless decode: p = l1*(l1-1)/2 + l0, l0 < l1
        int l1 = (int)((1.0f + sqrtf(8.0f * (float)p + 1.0f)) * 0.5f);
        if ((l1 * (l1 - 1)) >> 1 > p) l1--;
        if (((l1 + 1) * l1) >> 1 <= p) l1++;
        const int l0 = p - ((l1 * (l1 - 1)) >> 1);

        const int base2 = so[l0] * 256 + so[l1];
        float t2 = (sub == 0) ? th2[base2] : 0.f;   // order-2 term

        const float4* __restrict__ row4 = (const float4*)th3 + (size_t)base2 * 64;

        #pragma unroll 4
        for (int l2 = l1 + 1 + sub; l2 < LL; l2 += 4) {
            float4 r  = row4[l2];
            float4 xv = sx[l2];
            acc = fmaf(r.x, xv.x, acc);
            acc = fmaf(r.y, xv.y, acc);
            acc = fmaf(r.z, xv.z, acc);
            acc = fmaf(r.w, xv.w, acc);
        }
        acc += t2;
    }

    // order 0 + 1, folded into chunk-0 blocks (first 64 threads)
    if (chunk == 0 && tid < LL) {
        acc += th1[so[tid]];
        if (tid == 0) acc += th0[0];
    }

    // intra-block reduction
    #pragma unroll
    for (int off = 16; off > 0; off >>= 1)
        acc += __shfl_xor_sync(0xffffffffu, acc, off);
    const int warp = tid >> 5;
    if ((tid & 31) == 0) wsum[warp] = acc;
    __syncthreads();

    // cross-block: atomicAdd partial; last block for this batch finalizes
    if (tid == 0) {
        float t = 0.f;
        #pragma unroll
        for (int wi = 0; wi < 8; wi++) t += wsum[wi];
        atomicAdd(&g_acc[b], t);
        __threadfence();
        unsigned done = atomicAdd(&g_cnt[b], 1u);
        if (done == CHUNKS - 1) {
            __threadfence();
            out[b] = g_acc[b];
            g_acc[b] = 0.f;      // reset for next replay
            g_cnt[b] = 0u;
        }
    }
}

extern "C" void kernel_launch(void* const* d_in, const int* in_sizes, int n_in,
                              void* d_out, int out_size) {
    const float* x   = (const float*)d_in[0];   // (B, L*C) one-hot
    const float* th0 = (const float*)d_in[1];   // (1,)
    const float* th1 = (const float*)d_in[2];   // (L, C)
    const float* th2 = (const float*)d_in[3];   // (L*C, L*C)
    const float* th3 = (const float*)d_in[4];   // (L*C, L*C, L*C)
    float* out = (float*)d_out;                 // (B, 1)

    gp_kernel<<<BB * CHUNKS, 256>>>(x, th0, th1, th2, th3, out);
}